// round 17
// baseline (speedup 1.0000x reference)
#include <cuda_runtime.h>
#include <cuda.h>
#include <cuda_fp16.h>
#include <cstdint>
#include <math.h>

#define BB   128
#define TIN  256
#define DIN  64
#define HH   1024
#define G4   4096
#define TOUT 128
#define DOUT 128

#define K1   (HH + DIN)   // 1088
#define NKT1 (K1 / 16)    // 68 k16-tiles, layer 1
#define NKT2 (HH / 16)    // 64
#define NKC2 (HH / 8)     // legacy tf32 layout (modes 2/3)
#define NCTA 128
#define NSTG 4            // A-ring stages (16KB each)
#define CLS  4            // cluster size
#define MCAST 0xFu

// -------------------- device scratch --------------------
__device__ uint32_t g_W1h [512 * NKT1 * 64];  // [Wh1;Wi1] fp16-pair frag order
__device__ uint32_t g_W2h [512 * NKT2 * 64];  // Wh2
__device__ float    g_Wi2p[512 * NKC2 * 64];  // legacy tf32 (mode 2)
__device__ float    g_Wlp [ 16 * NKC2 * 64];  // legacy tf32 (mode 3)
__device__ __align__(256) __half g_xr16 [BB * TIN * DIN];
__device__ __align__(256) __half g_Hbuf16[2 * BB * HH];  // fp16 ping-pong h
__device__ float g_Hf32[BB * HH];             // t_last as float (mode 2 input)
__device__ float g_C   [BB * HH];
__device__ float g_XG2 [BB * G4];
__device__ float g_HS2 [TOUT * BB * HH];
__device__ unsigned int g_bar;

// -------------------- helpers --------------------
__device__ __forceinline__ float tf32r(float x) {
    uint32_t u;
    asm("cvt.rna.tf32.f32 %0, %1;" : "=r"(u) : "f"(x));
    return __uint_as_float(u);
}
__device__ __forceinline__ float sigf(float x) { return 1.0f / (1.0f + expf(-x)); }

__device__ __forceinline__ void mma8(float c[4], const uint32_t a[4], uint32_t b0, uint32_t b1) {
    asm volatile(
        "mma.sync.aligned.m16n8k8.row.col.f32.tf32.tf32.f32 "
        "{%0,%1,%2,%3}, {%4,%5,%6,%7}, {%8,%9}, {%0,%1,%2,%3};"
        : "+f"(c[0]), "+f"(c[1]), "+f"(c[2]), "+f"(c[3])
        : "r"(a[0]), "r"(a[1]), "r"(a[2]), "r"(a[3]), "r"(b0), "r"(b1));
}
__device__ __forceinline__ void mma16(float c[4], const uint32_t a[4], uint32_t b0, uint32_t b1) {
    asm volatile(
        "mma.sync.aligned.m16n8k16.row.col.f32.f16.f16.f32 "
        "{%0,%1,%2,%3}, {%4,%5,%6,%7}, {%8,%9}, {%0,%1,%2,%3};"
        : "+f"(c[0]), "+f"(c[1]), "+f"(c[2]), "+f"(c[3])
        : "r"(a[0]), "r"(a[1]), "r"(a[2]), "r"(a[3]), "r"(b0), "r"(b1));
}

__device__ __forceinline__ uint32_t s2u(const void* p) {
    uint32_t a;
    asm("{ .reg .u64 t; cvta.to.shared.u64 t, %1; cvt.u32.u64 %0, t; }" : "=r"(a) : "l"(p));
    return a;
}
__device__ __forceinline__ uint32_t ctarank() {
    uint32_t r;
    asm("mov.u32 %0, %%cluster_ctarank;" : "=r"(r));
    return r;
}
__device__ __forceinline__ void mbar_init(uint32_t a, int cnt) {
    asm volatile("mbarrier.init.shared.b64 [%0], %1;" :: "r"(a), "r"(cnt) : "memory");
}
__device__ __forceinline__ void mbar_arrive(uint32_t a) {
    asm volatile("mbarrier.arrive.shared.b64 _, [%0];" :: "r"(a) : "memory");
}
__device__ __forceinline__ void mbar_arrive_cluster(uint32_t local_addr, uint32_t rank) {
    asm volatile(
        "{\n\t.reg .b32 ra;\n\t"
        "mapa.shared::cluster.u32 ra, %0, %1;\n\t"
        "mbarrier.arrive.shared::cluster.b64 _, [ra];\n\t}"
        :: "r"(local_addr), "r"(rank) : "memory");
}
__device__ __forceinline__ void mbar_expect(uint32_t a, uint32_t bytes) {
    asm volatile("mbarrier.arrive.expect_tx.shared.b64 _, [%0], %1;" :: "r"(a), "r"(bytes) : "memory");
}
__device__ __forceinline__ void mbar_wait(uint32_t a, int ph) {
    asm volatile(
        "{\n\t.reg .pred P;\n"
        "W%=:\n\t"
        "mbarrier.try_wait.parity.acquire.cta.shared::cta.b64 P, [%0], %1, 0x989680;\n\t"
        "@P bra D%=;\n\t"
        "bra W%=;\n"
        "D%=:\n\t}"
        :: "r"(a), "r"(ph) : "memory");
}
__device__ __forceinline__ void tma3d_mc(uint32_t dst, const CUtensorMap* m,
                                         int x, int y, int z, uint32_t bar, uint16_t mask) {
    asm volatile(
        "cp.async.bulk.tensor.3d.shared::cluster.global.tile.mbarrier::complete_tx::bytes.multicast::cluster "
        "[%0], [%1, {%2,%3,%4}], [%5], %6;"
        :: "r"(dst), "l"(m), "r"(x), "r"(y), "r"(z), "r"(bar), "h"(mask) : "memory");
}
__device__ __forceinline__ void fence_async() {
    asm volatile("fence.proxy.async;" ::: "memory");
}
__device__ __forceinline__ void cluster_sync() {
    asm volatile("barrier.cluster.arrive.aligned;" ::: "memory");
    asm volatile("barrier.cluster.wait.aligned;" ::: "memory");
}

// Cooperative-groups-style grid barrier (proven R9-R16).
__device__ __forceinline__ void grid_barrier() {
    __syncthreads();
    if (threadIdx.x == 0) {
        __threadfence();
        unsigned int nb = (blockIdx.x == 0) ? (0x80000000u - (NCTA - 1u)) : 1u;
        unsigned int old = atomicAdd(&g_bar, nb);
        volatile unsigned int* vb = &g_bar;
        while ((((old ^ *vb) & 0x80000000u) == 0u)) { }
        __threadfence();
    }
    __syncthreads();
}

// -------------------- prep kernels --------------------
__global__ void permWh_kernel(const float* __restrict__ Wh, const float* __restrict__ Wx,
                              int which, int nkt, int total) {
    int i = blockIdx.x * blockDim.x + threadIdx.x;
    if (i >= total) return;
    uint32_t* dst = (which == 0) ? g_W1h : g_W2h;
    int reg  = i & 1;
    int lane = (i >> 1) & 31;
    int kt   = (i >> 6) % nkt;
    int nt   = i / (nkt * 64);
    int k = kt * 16 + reg * 8 + (lane & 3) * 2;
    int n = nt * 8 + (lane >> 2);
    float v0 = (k     < HH) ? Wh[k * G4 + n]           : Wx[(k - HH) * G4 + n];
    float v1 = (k + 1 < HH) ? Wh[(k + 1) * G4 + n]     : Wx[(k + 1 - HH) * G4 + n];
    uint32_t u = ((uint32_t)__half_as_ushort(__float2half_rn(v1)) << 16)
               |  (uint32_t)__half_as_ushort(__float2half_rn(v0));
    dst[i] = u;
}

__global__ void permW_kernel(const float* __restrict__ W, int which, int nkc, int ldsrc, int total) {
    int i = blockIdx.x * blockDim.x + threadIdx.x;
    if (i >= total) return;
    float* dst = (which == 2) ? g_Wi2p : g_Wlp;
    int reg  = i & 1;
    int lane = (i >> 1) & 31;
    int kc   = (i >> 6) % nkc;
    int nt   = i / (nkc * 64);
    int k = kc * 8 + reg * 4 + (lane & 3);
    int n = nt * 8 + (lane >> 2);
    dst[i] = tf32r(W[k * ldsrc + n]);
}

__global__ void roundx_kernel(const float* __restrict__ x, int total) {
    int i = blockIdx.x * blockDim.x + threadIdx.x;
    if (i < total) g_xr16[i] = __float2half_rn(x[i]);
}

__global__ void zero_kernel() {
    int i = blockIdx.x * blockDim.x + threadIdx.x;
    if (i < BB * HH) {
        ((uint32_t*)g_Hbuf16)[i] = 0u;
        g_C[i] = 0.0f;
    }
    if (i == 0) g_bar = 0u;
}

// -------------------- persistent LSTM layer kernel (fp16 + TMA multicast) ----
// 128 CTAs (32 clusters of 4) x 288 thr. Warps 0-7 consume (fp16 m16n8k16,
// fp32 accum), thread 256 = TMA producer. 4-stage ring of 16KB chunks; each
// cluster CTA multicasts a distinct 4KB slice (rows rank*32..+31) to all 4
// CTAs -> chip A-traffic /4. Stage-free protocol: consumers arrive LOCAL
// lfree (count 8); producer waits lfree, broadcasts one arrive to each CTA's
// empty (count 4), waits empty, then refills. First NSTG chunks skip the
// protocol (g-counter guard, derived parity). B slab SMEM-resident. Cell
// state fp32 in registers. CG grid barrier between steps; proxy fence
// orders generic h-stores before async-proxy TMA reads.
template<int LAYER>
__global__ void __launch_bounds__(288) __cluster_dims__(CLS, 1, 1)
lstm_persist(const __grid_constant__ CUtensorMap tmH,
             const __grid_constant__ CUtensorMap tmX,
             const float* __restrict__ bias, int nsteps)
{
    constexpr int NKT = (LAYER == 1) ? NKT1 : NKT2;   // k16-tiles
    constexpr int NC  = (LAYER == 1) ? 17 : 16;       // 64-k chunks per step

    extern __shared__ float smraw[];
    const uint32_t rawB = s2u(smraw);
    const uint32_t aB   = (rawB + 1023u) & ~1023u;   // 1024B-aligned TMA ring
    uint32_t* sA  = (uint32_t*)(smraw + ((aB - rawB) >> 2));  // NSTG x 4096 u32
    uint32_t* sBh = sA + NSTG * 4096;                // B slab, frag pairs
    const uint32_t barB = s2u(sBh + 4 * NKT * 64);
    // stage s: full @ s*32, empty @ s*32+8, lfree @ s*32+16

    const int tid = threadIdx.x, w = tid >> 5, lane = tid & 31, cta = blockIdx.x;
    const uint32_t rank = ctarank();
    const bool producer = (tid == 256);
    const bool consumer = (tid < 256);

    // ---- load B slab into SMEM (once per layer) ----
    {
        const uint32_t* Wp = (LAYER == 1) ? g_W1h : g_W2h;
        #pragma unroll
        for (int q = 0; q < 4; ++q) {
            const uint4* src = (const uint4*)(Wp + (size_t)(cta + q * 128) * (NKT * 64));
            uint4* dst = (uint4*)(sBh + q * NKT * 64);
            for (int i = tid; i < NKT * 16; i += 288) dst[i] = src[i];
        }
    }
    if (tid == 0) {
        #pragma unroll
        for (int s = 0; s < NSTG; ++s) {
            mbar_init(barB + s * 32 + 0, 1);    // full: one local expect_tx arrive
            mbar_init(barB + s * 32 + 8, 4);    // empty: one broadcast per cluster CTA
            mbar_init(barB + s * 32 + 16, 8);   // lfree: 8 local consumer warps
        }
        asm volatile("fence.proxy.async.shared::cta;" ::: "memory");
    }
    __syncthreads();
    cluster_sync();   // peers' mbarriers live before any multicast TMA

    // ---- per-thread constants ----
    const int j0 = cta * 8 + (lane & 3) * 2;

    float bI[2], bF[2], bG[2], bO[2];
    float xg[4][4];
    float creg[4] = {0.f, 0.f, 0.f, 0.f};
    if (consumer) {
        if (LAYER == 1) {
            #pragma unroll
            for (int u = 0; u < 2; ++u) {
                bI[u] = bias[j0 + u];          bF[u] = bias[HH + j0 + u];
                bG[u] = bias[2 * HH + j0 + u]; bO[u] = bias[3 * HH + j0 + u];
            }
        } else {
            #pragma unroll
            for (int cr = 0; cr < 4; ++cr) {
                int m = (w & 7) * 16 + (lane >> 2) + ((cr >> 1) << 3);
                int j = j0 + (cr & 1);
                xg[cr][0] = __ldcg(&g_XG2[m * G4 + j]);
                xg[cr][1] = __ldcg(&g_XG2[m * G4 + HH + j]);
                xg[cr][2] = __ldcg(&g_XG2[m * G4 + 2 * HH + j]);
                xg[cr][3] = __ldcg(&g_XG2[m * G4 + 3 * HH + j]);
                creg[cr]  = __ldcg(&g_C[m * HH + j]);
            }
        }
    }
    __syncthreads();

    int g = 0;                 // producer global chunk counter
    int cs = 0, cp = 0;        // consumer stage+phase
    int rd = 0;

    for (int t = 0; t < nsteps; ++t) {
        if (producer) {
            fence_async();   // order prior generic h-stores before async reads
            for (int c = 0; c < NC; ++c) {
                int s = g & (NSTG - 1);
                if (g >= NSTG) {
                    int par = ((g >> 2) + 1) & 1;
                    mbar_wait(barB + s * 32 + 16, par);     // my consumers freed s
                    #pragma unroll
                    for (uint32_t r = 0; r < CLS; ++r)       // tell all producers
                        mbar_arrive_cluster(barB + s * 32 + 8, r);
                    mbar_wait(barB + s * 32 + 8, par);      // all CTAs freed s
                }
                mbar_expect(barB + s * 32, 16384);
                uint32_t d = aB + s * 16384 + rank * 4096;
                if (LAYER == 1 && c == 16)
                    tma3d_mc(d, &tmX, 0, t, (int)rank * 32, barB + s * 32, MCAST);
                else
                    tma3d_mc(d, &tmH, c * 64, (int)rank * 32, rd, barB + s * 32, MCAST);
                ++g;
            }
        }

        float acc[4][4];
        #pragma unroll
        for (int q = 0; q < 4; ++q)
            #pragma unroll
            for (int r = 0; r < 4; ++r) acc[q][r] = 0.f;

        if (consumer) {
            const int gg2 = lane >> 2;
            const int lp  = lane & 3;
            const int m0  = (w & 7) * 16 + gg2;
            const int m1  = m0 + 8;
            const int sw0 = (m0 & 7) << 2;
            const int sw1 = (m1 & 7) << 2;

            for (int c = 0; c < NC; ++c) {
                uint2 bfr[4][4];
                #pragma unroll
                for (int kk = 0; kk < 4; ++kk) {
                    int kt = c * 4 + kk;
                    #pragma unroll
                    for (int q = 0; q < 4; ++q)
                        bfr[kk][q] = *(const uint2*)(sBh + ((q * NKT + kt) * 32 + lane) * 2);
                }

                mbar_wait(barB + cs * 32, cp);
                const uint32_t* hb = sA + cs * 4096;

                #pragma unroll
                for (int kk = 0; kk < 4; ++kk) {
                    int p0 = kk * 8 + lp;
                    int p2 = p0 + 4;
                    uint32_t a[4];
                    a[0] = hb[m0 * 32 + (p0 ^ sw0)];
                    a[1] = hb[m1 * 32 + (p0 ^ sw1)];
                    a[2] = hb[m0 * 32 + (p2 ^ sw0)];
                    a[3] = hb[m1 * 32 + (p2 ^ sw1)];
                    #pragma unroll
                    for (int q = 0; q < 4; ++q)
                        mma16(acc[q], a, bfr[kk][q].x, bfr[kk][q].y);
                }
                if (lane == 0) mbar_arrive(barB + cs * 32 + 16);  // local lfree
                cs = (cs + 1) & (NSTG - 1); if (cs == 0) cp ^= 1;
            }

            // ---- epilogue: gates (order unchanged), packed stores ----
            #pragma unroll
            for (int mt = 0; mt < 2; ++mt) {
                float hv[2], cv[2];
                #pragma unroll
                for (int u = 0; u < 2; ++u) {
                    int cr = mt * 2 + u;
                    float gi, gf, gg, go;
                    if (LAYER == 1) {
                        gi = acc[0][cr] + bI[u]; gf = acc[1][cr] + bF[u];
                        gg = acc[2][cr] + bG[u]; go = acc[3][cr] + bO[u];
                    } else {
                        gi = acc[0][cr] + xg[cr][0]; gf = acc[1][cr] + xg[cr][1];
                        gg = acc[2][cr] + xg[cr][2]; go = acc[3][cr] + xg[cr][3];
                    }
                    float cn = sigf(gf) * creg[cr] + sigf(gi) * tanhf(gg);
                    float hn = sigf(go) * tanhf(cn);
                    creg[cr] = cn;
                    hv[u] = hn; cv[u] = cn;
                }
                int m = (w & 7) * 16 + (lane >> 2) + (mt << 3);
                __half2 hh = __floats2half2_rn(hv[0], hv[1]);
                *((__half2*)&g_Hbuf16[(rd ^ 1) * (BB * HH) + m * HH + j0]) = hh;
                if (LAYER == 2)
                    __stcg((float2*)&g_HS2[(size_t)t * (BB * HH) + m * HH + j0],
                           make_float2(hv[0], hv[1]));
                if (LAYER == 1 && t == nsteps - 1) {
                    __stcg((float2*)&g_C[m * HH + j0],    make_float2(cv[0], cv[1]));
                    __stcg((float2*)&g_Hf32[m * HH + j0], make_float2(hv[0], hv[1]));
                }
            }
        }

        grid_barrier();
        rd ^= 1;
    }
    cluster_sync();   // no CTA exits while peer multicasts could target it
}

// -------------------- one-shot GEMMs (tf32 legacy; verbatim-proven) --------------------
template<int MODE>
__global__ void __launch_bounds__(256)
gemm_kernel(const float* __restrict__ bias, float* __restrict__ out) {
    constexpr int NKC = NKC2;
    constexpr int NC  = HH / 32;

    __shared__ float sAs[2][4096];
    const int tid = threadIdx.x, w = tid >> 5, lane = tid & 31, cta = blockIdx.x;

    const float* Aptr = (MODE == 3) ? (g_HS2 + blockIdx.x * (BB * HH)) : g_Hf32;
    const float* Wp   = (MODE == 3) ? g_Wlp : g_Wi2p;

    float acc[4][4];
    #pragma unroll
    for (int q = 0; q < 4; ++q)
        #pragma unroll
        for (int r = 0; r < 4; ++r) acc[q][r] = 0.0f;

    auto stage = [&](int c, float* dstbuf) {
        #pragma unroll
        for (int jj = 0; jj < 4; ++jj) {
            int s  = tid + jj * 256;
            int m  = s >> 3;
            int kq = s & 7;
            float4 v = *(const float4*)(Aptr + m * HH + c * 32 + kq * 4);
            int kk  = kq >> 1;
            int reg = (kq & 1) * 2 + ((m >> 3) & 1);
            int hi3 = (m & 7) ^ kq;
            *(float4*)(dstbuf + kk * 1024 + ((m >> 4) * 4 + reg) * 32 + hi3 * 4) = v;
        }
    };

    stage(0, sAs[0]);
    __syncthreads();

    for (int c = 0; c < NC; ++c) {
        const float* buf = sAs[c & 1];
        if (c + 1 < NC) stage(c + 1, sAs[(c + 1) & 1]);

        float2 bfr[4][4];
        #pragma unroll
        for (int kk = 0; kk < 4; ++kk) {
            int kc = c * 4 + kk;
            #pragma unroll
            for (int q = 0; q < 4; ++q) {
                int nt = (MODE == 3) ? (blockIdx.y * 4 + q) : (cta + q * 128);
                bfr[kk][q] = *(const float2*)(Wp + ((size_t)(nt * NKC + kc) * 32 + lane) * 2);
            }
        }

        #pragma unroll
        for (int kk = 0; kk < 4; ++kk) {
            uint32_t a[4];
            #pragma unroll
            for (int r = 0; r < 4; ++r) {
                int hi3 = (lane >> 2) ^ (kk * 2 + (r >> 1));
                a[r] = __float_as_uint(buf[kk * 1024 + (w * 4 + r) * 32 + hi3 * 4 + (lane & 3)]);
            }
            #pragma unroll
            for (int q = 0; q < 4; ++q)
                mma8(acc[q], a, __float_as_uint(bfr[kk][q].x), __float_as_uint(bfr[kk][q].y));
        }
        __syncthreads();
    }

    #pragma unroll
    for (int cr = 0; cr < 4; ++cr) {
        int m    = w * 16 + (lane >> 2) + ((cr >> 1) << 3);
        int jloc = (lane & 3) * 2 + (cr & 1);
        if (MODE == 3) {
            #pragma unroll
            for (int q = 0; q < 4; ++q) {
                int d = blockIdx.y * 32 + q * 8 + jloc;
                out[m * (TOUT * DOUT) + blockIdx.x * DOUT + d] = acc[q][cr] + bias[d];
            }
        } else {
            #pragma unroll
            for (int q = 0; q < 4; ++q) {
                int n = q * HH + cta * 8 + jloc;
                g_XG2[m * G4 + n] = acc[q][cr] + bias[n];
            }
        }
    }
}

// -------------------- launch --------------------
typedef CUresult (*EncodeFn)(CUtensorMap*, CUtensorMapDataType, cuuint32_t, void*,
                             const cuuint64_t*, const cuuint64_t*, const cuuint32_t*,
                             const cuuint32_t*, CUtensorMapInterleave, CUtensorMapSwizzle,
                             CUtensorMapL2promotion, CUtensorMapFloatOOBfill);

// smem: align slack + 64KB A ring + fp16 B slab + barrier block
#define SMEM1 (1024 + 65536 + 4 * NKT1 * 64 * 4 + 128)   // 136,320 B
#define SMEM2 (1024 + 65536 + 4 * NKT2 * 64 * 4 + 128)   // 132,224 B

extern "C" void kernel_launch(void* const* d_in, const int* in_sizes, int n_in,
                              void* d_out, int out_size) {
    const float* x    = (const float*)d_in[0];
    const float* Wi1  = (const float*)d_in[1];
    const float* Wh1  = (const float*)d_in[2];
    const float* b1   = (const float*)d_in[3];
    const float* Wi2  = (const float*)d_in[4];
    const float* Wh2  = (const float*)d_in[5];
    const float* b2   = (const float*)d_in[6];
    const float* Wlin = (const float*)d_in[7];
    const float* blin = (const float*)d_in[8];
    float* out = (float*)d_out;

    // ---- prep ----
    {
        int n;
        n = 512 * NKT1 * 64;
        permWh_kernel<<<(n + 255) / 256, 256>>>(Wh1, Wi1, 0, NKT1, n);
        n = 512 * NKT2 * 64;
        permWh_kernel<<<(n + 255) / 256, 256>>>(Wh2, nullptr, 1, NKT2, n);
        n = 512 * NKC2 * 64;
        permW_kernel<<<(n + 255) / 256, 256>>>(Wi2, 2, NKC2, G4, n);
        n = 16 * NKC2 * 64;
        permW_kernel<<<(n + 255) / 256, 256>>>(Wlin, 3, NKC2, DOUT, n);
        n = BB * TIN * DIN;
        roundx_kernel<<<(n + 255) / 256, 256>>>(x, n);
        zero_kernel<<<(BB * HH + 255) / 256, 256>>>();
    }

    // ---- tensor maps (fp16; SW128; 4KB slice boxes for multicast) ----
    void* encP = nullptr;
    cudaDriverEntryPointQueryResult qr;
    cudaGetDriverEntryPointByVersion("cuTensorMapEncodeTiled", &encP, 12000,
                                     cudaEnableDefault, &qr);
    EncodeFn enc = (EncodeFn)encP;

    void* hAddr = nullptr; cudaGetSymbolAddress(&hAddr, g_Hbuf16);
    void* xAddr = nullptr; cudaGetSymbolAddress(&xAddr, g_xr16);

    CUtensorMap tmH, tmX;
    {
        // h: [1024 halves][128 rows][2 bufs]; box = 64 halves x 32 rows (4KB slice)
        cuuint64_t dims[3] = {1024, 128, 2};
        cuuint64_t str[2]  = {2048, 262144};
        cuuint32_t box[3]  = {64, 32, 1};
        cuuint32_t es[3]   = {1, 1, 1};
        enc(&tmH, CU_TENSOR_MAP_DATA_TYPE_UINT16, 3, hAddr, dims, str, box, es,
            CU_TENSOR_MAP_INTERLEAVE_NONE, CU_TENSOR_MAP_SWIZZLE_128B,
            CU_TENSOR_MAP_L2_PROMOTION_L2_128B, CU_TENSOR_MAP_FLOAT_OOB_FILL_NONE);
    }
    {
        // x: [64 halves][256 t][128 batch]; box = 64 x 1 x 32 (4KB slice)
        cuuint64_t dims[3] = {64, 256, 128};
        cuuint64_t str[2]  = {128, 32768};
        cuuint32_t box[3]  = {64, 1, 32};
        cuuint32_t es[3]   = {1, 1, 1};
        enc(&tmX, CU_TENSOR_MAP_DATA_TYPE_UINT16, 3, xAddr, dims, str, box, es,
            CU_TENSOR_MAP_INTERLEAVE_NONE, CU_TENSOR_MAP_SWIZZLE_128B,
            CU_TENSOR_MAP_L2_PROMOTION_L2_128B, CU_TENSOR_MAP_FLOAT_OOB_FILL_NONE);
    }

    cudaFuncSetAttribute(lstm_persist<1>, cudaFuncAttributeMaxDynamicSharedMemorySize, SMEM1);
    cudaFuncSetAttribute(lstm_persist<2>, cudaFuncAttributeMaxDynamicSharedMemorySize, SMEM2);

    // ---- layer 1: 256 steps, persistent, fp16 + multicast ----
    lstm_persist<1><<<NCTA, 288, SMEM1>>>(tmH, tmX, b1, TIN);
    // ---- xg2 = t_last @ Wi2 + b2 (t_last saved as float in g_Hf32) ----
    gemm_kernel<2><<<128, 256>>>(b2, nullptr);
    // ---- layer 2: 128 steps, persistent (h,c carry over) ----
    lstm_persist<2><<<NCTA, 288, SMEM2>>>(tmH, tmX, nullptr, TOUT);
    // ---- final projection ----
    gemm_kernel<3><<<dim3(TOUT, 4), 256>>>(blin, out);
}